// round 3
// baseline (speedup 1.0000x reference)
#include <cuda_runtime.h>
#include <cuda_bf16.h>
#include <cstdint>
#include <math.h>

#define NSTEPS 100
#define NU     128
#define BTOT   200000
#define TILE_M 128
#define NTHREADS 256

// ---------------- SMEM layout (dynamic) ----------------
// H ping/pong: 128 rows x 128 bf16 cols = 256B/row, XOR-swizzled in 16B chunks.
#define SM_HP   0
#define SM_HQ   32768
#define SM_F32  65536

// float region indices (within fA)
#define F_W0A   0
#define F_W0B   128
#define F_W3A   256
#define F_W3B   384
#define F_BE0   512
#define F_BE1   640
#define F_BE2   768
#define F_COEF  896
#define F_INVAS 1024
#define F_BSQ   1152
#define F_B3    1280      // 2 floats
#define F_XS    1284      // 128 x float2 = 256 floats (x state mirror)
#define F_PP    1540      // 8 warps x 128 rows x float2 = 2048 floats
#define F_TOTAL (F_PP + 2048)
#define SMEM_TOTAL (SM_F32 + F_TOTAL * 4)

// ---------------- helpers ----------------
static __device__ __forceinline__ uint32_t smem_u32(const void* p) {
    uint32_t a;
    asm("{ .reg .u64 t; cvta.to.shared.u64 t, %1; cvt.u32.u64 %0, t; }" : "=r"(a) : "l"(p));
    return a;
}

static __device__ __forceinline__ uint32_t pack_bf16(float lo, float hi) {
    __nv_bfloat162 h = __floats2bfloat162_rn(lo, hi);
    return *reinterpret_cast<uint32_t*>(&h);
}

#define LDSM4(r0, r1, r2, r3, addr)                                              \
    asm volatile("ldmatrix.sync.aligned.m8n8.x4.shared.b16 {%0,%1,%2,%3}, [%4];" \
                 : "=r"(r0), "=r"(r1), "=r"(r2), "=r"(r3) : "r"(addr))

static __device__ __forceinline__ void mma16816(float c[4],
        uint32_t a0, uint32_t a1, uint32_t a2, uint32_t a3,
        uint32_t b0, uint32_t b1) {
    asm volatile(
        "mma.sync.aligned.m16n8k16.row.col.f32.bf16.bf16.f32 "
        "{%0,%1,%2,%3}, {%4,%5,%6,%7}, {%8,%9}, {%0,%1,%2,%3};"
        : "+f"(c[0]), "+f"(c[1]), "+f"(c[2]), "+f"(c[3])
        : "r"(a0), "r"(a1), "r"(a2), "r"(a3), "r"(b0), "r"(b1));
}

static __device__ __forceinline__ void sts128(uint32_t addr, uint32_t a, uint32_t b,
                                              uint32_t c, uint32_t d) {
    asm volatile("st.shared.v4.b32 [%0], {%1,%2,%3,%4};"
                 :: "r"(addr), "r"(b), "r"(c), "r"(d), "r"(a) : "memory");
}
static __device__ __forceinline__ void sts128v(uint32_t addr, uint32_t a, uint32_t b,
                                               uint32_t c, uint32_t d) {
    asm volatile("st.shared.v4.b32 [%0], {%1,%2,%3,%4};"
                 :: "r"(addr), "r"(a), "r"(b), "r"(c), "r"(d) : "memory");
}
static __device__ __forceinline__ void sts32(uint32_t addr, uint32_t v) {
    asm volatile("st.shared.b32 [%0], %1;" :: "r"(addr), "r"(v) : "memory");
}

__global__ void __launch_bounds__(NTHREADS, 2)
ddpm_kernel(const float* __restrict__ noise, const float* __restrict__ z,
            const float* __restrict__ W0, const float* __restrict__ b0,
            const float* __restrict__ W1, const float* __restrict__ b1,
            const float* __restrict__ W2, const float* __restrict__ b2,
            const float* __restrict__ W3, const float* __restrict__ b3,
            const float* __restrict__ E0, const float* __restrict__ E1,
            const float* __restrict__ E2, float* __restrict__ out)
{
    extern __shared__ char smem_raw[];
    const uint32_t sb = smem_u32(smem_raw);
    float* fA = (float*)(smem_raw + SM_F32);
    float2* fXS = (float2*)&fA[F_XS];
    float2* fPP = (float2*)&fA[F_PP];

    const int tid  = threadIdx.x;
    const int lane = tid & 31;
    const int w    = tid >> 5;          // 0..7
    const int row128 = tid & 127;      // row this (half-)thread serves in layer0
    const int jh     = tid >> 7;        // 0 or 1: which 64-col half in layer0
    const int sample = blockIdx.x * TILE_M + row128;
    const bool owner = (tid < 128);
    const bool valid = owner && (sample < BTOT);

    // ---- prologue: small tensors into SMEM ----
    if (tid < 128) {
        fA[F_W0A + tid] = W0[tid];
        fA[F_W0B + tid] = W0[NU + tid];
        fA[F_W3A + tid] = W3[tid * 2 + 0];
        fA[F_W3B + tid] = W3[tid * 2 + 1];
    }
    if (tid < 2) fA[F_B3 + tid] = b3[tid];

    if (tid == 0) {
        double prod = 1.0;
        for (int t = 0; t < NSTEPS; t++) {
            double xl = -6.0 + 12.0 * (double)t / 99.0;
            double beta = (1.0 / (1.0 + exp(-xl))) * (0.005 - 1e-5) + 1e-5;
            double alpha = 1.0 - beta;
            prod *= alpha;
            fA[F_COEF + t]  = (float)(beta / sqrt(1.0 - prod));
            fA[F_INVAS + t] = (float)(1.0 / sqrt(alpha));
            fA[F_BSQ + t]   = (float)sqrt(beta);
        }
    }

    // ---- weight B-fragments in registers (per-warp 16-col N slice) ----
    // m16n8k16 B frag: lane holds B[k][n], n = w*16 + nt*8 + lane/4, k = kc*16 + (lane%4)*2 (+8)
    uint32_t B1[2][8][2], B2[2][8][2];
    {
        const int n0 = w * 16 + (lane >> 2);
        const int kb = (lane & 3) * 2;
        #pragma unroll
        for (int nt = 0; nt < 2; nt++) {
            int n = n0 + nt * 8;
            #pragma unroll
            for (int kc = 0; kc < 8; kc++) {
                int k0 = kc * 16 + kb;
                B1[nt][kc][0] = pack_bf16(W1[k0 * NU + n],       W1[(k0 + 1) * NU + n]);
                B1[nt][kc][1] = pack_bf16(W1[(k0 + 8) * NU + n], W1[(k0 + 9) * NU + n]);
                B2[nt][kc][0] = pack_bf16(W2[k0 * NU + n],       W2[(k0 + 1) * NU + n]);
                B2[nt][kc][1] = pack_bf16(W2[(k0 + 8) * NU + n], W2[(k0 + 9) * NU + n]);
            }
        }
    }

    // ---- per-thread x state (owner threads), mirrored in SMEM ----
    float x0 = 0.f, x1 = 0.f;
    if (valid) {
        float2 n2 = ((const float2*)noise)[sample];
        x0 = n2.x; x1 = n2.y;
    }
    if (owner) fXS[row128] = make_float2(x0, x1);

    // per-lane ldmatrix constants
    const uint32_t r_lo    = (uint32_t)(lane & 7);
    const uint32_t half    = (uint32_t)((lane >> 3) & 1);
    const uint32_t khalf   = (uint32_t)(lane >> 4);
    const uint32_t lrowoff = (half * 8 + r_lo) * 256;
    const uint32_t erow    = (uint32_t)(lane >> 2);      // 0..7
    const uint32_t ecolq   = (uint32_t)(lane & 3);

    const uint32_t sbHP = sb + SM_HP;
    const uint32_t sbHQ = sb + SM_HQ;
    // layer0 store base: this thread writes row row128, cols [jh*64, jh*64+64)
    const uint32_t l0row = sbHP + (uint32_t)row128 * 256;
    const uint32_t l0xor = (uint32_t)(row128 & 7);

    __syncthreads();

    #pragma unroll 1
    for (int i = 0; i < NSTEPS; i++) {
        const int t = NSTEPS - 1 - i;

        // prefetch z (owner threads)
        float zc0 = 0.f, zc1 = 0.f;
        if (valid) {
            float2 zz = ((const float2*)z)[(size_t)i * BTOT + sample];
            zc0 = zz.x; zc1 = zz.y;
        }

        // per-step fused bias+embedding (threads 0-127 write col tid)
        if (owner) {
            fA[F_BE0 + tid] = b0[tid] + E0[t * NU + tid];
            fA[F_BE1 + tid] = b1[tid] + E1[t * NU + tid];
            fA[F_BE2 + tid] = b2[tid] + E2[t * NU + tid];
        }
        __syncthreads();

        // ---- layer 0 (fp32 scalar): h1 = relu(x @ W0 + be0) -> HP ----
        {
            float2 xv = fXS[row128];
            const int j0 = jh * 64;
            #pragma unroll
            for (int jj = 0; jj < 64; jj += 8) {
                int j = j0 + jj;
                float4 wa0 = *(const float4*)&fA[F_W0A + j];
                float4 wa1 = *(const float4*)&fA[F_W0A + j + 4];
                float4 wb0 = *(const float4*)&fA[F_W0B + j];
                float4 wb1 = *(const float4*)&fA[F_W0B + j + 4];
                float4 be0v = *(const float4*)&fA[F_BE0 + j];
                float4 be1v = *(const float4*)&fA[F_BE0 + j + 4];
                float v0 = fmaxf(fmaf(xv.x, wa0.x, fmaf(xv.y, wb0.x, be0v.x)), 0.f);
                float v1 = fmaxf(fmaf(xv.x, wa0.y, fmaf(xv.y, wb0.y, be0v.y)), 0.f);
                float v2 = fmaxf(fmaf(xv.x, wa0.z, fmaf(xv.y, wb0.z, be0v.z)), 0.f);
                float v3 = fmaxf(fmaf(xv.x, wa0.w, fmaf(xv.y, wb0.w, be0v.w)), 0.f);
                float v4 = fmaxf(fmaf(xv.x, wa1.x, fmaf(xv.y, wb1.x, be1v.x)), 0.f);
                float v5 = fmaxf(fmaf(xv.x, wa1.y, fmaf(xv.y, wb1.y, be1v.y)), 0.f);
                float v6 = fmaxf(fmaf(xv.x, wa1.z, fmaf(xv.y, wb1.z, be1v.z)), 0.f);
                float v7 = fmaxf(fmaf(xv.x, wa1.w, fmaf(xv.y, wb1.w, be1v.w)), 0.f);
                uint32_t addr = l0row + ((((uint32_t)(j >> 3)) ^ l0xor) << 4);
                sts128v(addr, pack_bf16(v0, v1), pack_bf16(v2, v3),
                              pack_bf16(v4, v5), pack_bf16(v6, v7));
            }
        }
        __syncthreads();

        // ---- GEMM1: HQ = relu(HP @ W1 + be1) ----
        #pragma unroll 1
        for (int mt = 0; mt < 8; mt++) {
            float c[2][4];
            #pragma unroll
            for (int nt = 0; nt < 2; nt++)
                #pragma unroll
                for (int q = 0; q < 4; q++) c[nt][q] = 0.f;

            const uint32_t abase = sbHP + (uint32_t)mt * 4096 + lrowoff;
            #pragma unroll
            for (int kc = 0; kc < 8; kc++) {
                uint32_t a0, a1, a2, a3;
                uint32_t aaddr = abase + ((((uint32_t)(kc * 2) + khalf) ^ r_lo) << 4);
                LDSM4(a0, a1, a2, a3, aaddr);
                mma16816(c[0], a0, a1, a2, a3, B1[0][kc][0], B1[0][kc][1]);
                mma16816(c[1], a0, a1, a2, a3, B1[1][kc][0], B1[1][kc][1]);
            }

            const uint32_t row0 = (uint32_t)mt * 16 + erow;
            const uint32_t dst0 = sbHQ + row0 * 256;
            #pragma unroll
            for (int nt = 0; nt < 2; nt++) {
                int col = w * 16 + nt * 8 + (int)ecolq * 2;
                float bea = fA[F_BE1 + col];
                float beb = fA[F_BE1 + col + 1];
                float v0 = fmaxf(c[nt][0] + bea, 0.f);
                float v1 = fmaxf(c[nt][1] + beb, 0.f);
                float v2 = fmaxf(c[nt][2] + bea, 0.f);
                float v3 = fmaxf(c[nt][3] + beb, 0.f);
                uint32_t chunk = (uint32_t)(w * 2 + nt);
                uint32_t a0addr = dst0 + ((chunk ^ erow) << 4) + ecolq * 4;
                sts32(a0addr,        pack_bf16(v0, v1));
                sts32(a0addr + 2048, pack_bf16(v2, v3));
            }
        }
        __syncthreads();

        // ---- GEMM2 + fused layer3: pred partials per warp ----
        #pragma unroll 1
        for (int mt = 0; mt < 8; mt++) {
            float c[2][4];
            #pragma unroll
            for (int nt = 0; nt < 2; nt++)
                #pragma unroll
                for (int q = 0; q < 4; q++) c[nt][q] = 0.f;

            const uint32_t abase = sbHQ + (uint32_t)mt * 4096 + lrowoff;
            #pragma unroll
            for (int kc = 0; kc < 8; kc++) {
                uint32_t a0, a1, a2, a3;
                uint32_t aaddr = abase + ((((uint32_t)(kc * 2) + khalf) ^ r_lo) << 4);
                LDSM4(a0, a1, a2, a3, aaddr);
                mma16816(c[0], a0, a1, a2, a3, B2[0][kc][0], B2[0][kc][1]);
                mma16816(c[1], a0, a1, a2, a3, B2[1][kc][0], B2[1][kc][1]);
            }

            // epilogue: v = relu(c + be2); partial pred = v . W3 over this warp's cols
            float pA0 = 0.f, pA1 = 0.f, pB0 = 0.f, pB1 = 0.f;
            #pragma unroll
            for (int nt = 0; nt < 2; nt++) {
                int col = w * 16 + nt * 8 + (int)ecolq * 2;
                float bea = fA[F_BE2 + col];
                float beb = fA[F_BE2 + col + 1];
                float wa0 = fA[F_W3A + col], wa1 = fA[F_W3A + col + 1];
                float wb0 = fA[F_W3B + col], wb1 = fA[F_W3B + col + 1];
                float v0 = fmaxf(c[nt][0] + bea, 0.f);
                float v1 = fmaxf(c[nt][1] + beb, 0.f);
                float v2 = fmaxf(c[nt][2] + bea, 0.f);
                float v3 = fmaxf(c[nt][3] + beb, 0.f);
                pA0 = fmaf(v0, wa0, fmaf(v1, wa1, pA0));
                pA1 = fmaf(v0, wb0, fmaf(v1, wb1, pA1));
                pB0 = fmaf(v2, wa0, fmaf(v3, wa1, pB0));
                pB1 = fmaf(v2, wb0, fmaf(v3, wb1, pB1));
            }
            // quad reduce over ecolq (lanes differing in bits 0-1)
            pA0 += __shfl_xor_sync(0xffffffffu, pA0, 1);
            pA1 += __shfl_xor_sync(0xffffffffu, pA1, 1);
            pB0 += __shfl_xor_sync(0xffffffffu, pB0, 1);
            pB1 += __shfl_xor_sync(0xffffffffu, pB1, 1);
            pA0 += __shfl_xor_sync(0xffffffffu, pA0, 2);
            pA1 += __shfl_xor_sync(0xffffffffu, pA1, 2);
            pB0 += __shfl_xor_sync(0xffffffffu, pB0, 2);
            pB1 += __shfl_xor_sync(0xffffffffu, pB1, 2);
            if (ecolq == 0) {
                int rA = mt * 16 + (int)erow;
                fPP[w * 128 + rA]     = make_float2(pA0, pA1);
                fPP[w * 128 + rA + 8] = make_float2(pB0, pB1);
            }
        }
        __syncthreads();

        // ---- x update (owner threads) ----
        if (owner) {
            float p0 = fA[F_B3 + 0], p1 = fA[F_B3 + 1];
            #pragma unroll
            for (int ww = 0; ww < 8; ww++) {
                float2 v = fPP[ww * 128 + row128];
                p0 += v.x; p1 += v.y;
            }
            float cf = fA[F_COEF + t], ia = fA[F_INVAS + t], bq = fA[F_BSQ + t];
            x0 = (x0 - cf * p0) * ia + bq * zc0;
            x1 = (x1 - cf * p1) * ia + bq * zc1;
            fXS[row128] = make_float2(x0, x1);
        }
        __syncthreads();   // xs / BE / HP / HQ / PP reuse next step
    }

    if (valid) {
        ((float2*)out)[sample] = make_float2(x0, x1);
    }
}

extern "C" void kernel_launch(void* const* d_in, const int* in_sizes, int n_in,
                              void* d_out, int out_size) {
    (void)in_sizes; (void)n_in; (void)out_size;
    const float* noise = (const float*)d_in[0];
    const float* z     = (const float*)d_in[1];
    const float* W0    = (const float*)d_in[2];
    const float* b0    = (const float*)d_in[3];
    const float* W1    = (const float*)d_in[4];
    const float* b1    = (const float*)d_in[5];
    const float* W2    = (const float*)d_in[6];
    const float* b2    = (const float*)d_in[7];
    const float* W3    = (const float*)d_in[8];
    const float* b3    = (const float*)d_in[9];
    const float* E0    = (const float*)d_in[10];
    const float* E1    = (const float*)d_in[11];
    const float* E2    = (const float*)d_in[12];
    float* out = (float*)d_out;

    cudaFuncSetAttribute(ddpm_kernel, cudaFuncAttributeMaxDynamicSharedMemorySize, SMEM_TOTAL);

    dim3 grid((BTOT + TILE_M - 1) / TILE_M);
    ddpm_kernel<<<grid, NTHREADS, SMEM_TOTAL>>>(noise, z, W0, b0, W1, b1, W2, b2,
                                                W3, b3, E0, E1, E2, out);
}

// round 4
// speedup vs baseline: 1.1371x; 1.1371x over previous
#include <cuda_runtime.h>
#include <cuda_bf16.h>
#include <cstdint>
#include <math.h>

#define NSTEPS 100
#define NU     128
#define BTOT   200000
#define NTHREADS 256
// CTA handles two 64-row tiles (a, b) = 128 samples
#define CTA_SAMPLES 128

// ---------------- SMEM layout ----------------
#define SM_H1A  0
#define SM_H1B  16384
#define SM_H2A  32768
#define SM_H2B  49152
#define SM_F32  65536

// float indices within fA
#define F_W0A   0
#define F_W0B   128
#define F_W3A   256
#define F_W3B   384
#define F_BE0   512      // [2][128] ping-pong by step parity
#define F_BE1   768      // [2][128]
#define F_BE2   1024     // [2][128]
#define F_COEF  1280
#define F_INVAS 1380
#define F_BSQ   1480
#define F_B3    1580     // 2 floats (pad to 1584)
#define F_XS    1584     // float2 [2 tiles][64 rows] = 256 floats
#define F_PP    1840     // float2 [4 warps][64 rows] = 512 floats
#define F_TOTAL 2352
#define SMEM_TOTAL (SM_F32 + F_TOTAL * 4)

// ---------------- helpers ----------------
static __device__ __forceinline__ uint32_t smem_u32(const void* p) {
    uint32_t a;
    asm("{ .reg .u64 t; cvta.to.shared.u64 t, %1; cvt.u32.u64 %0, t; }" : "=r"(a) : "l"(p));
    return a;
}
static __device__ __forceinline__ uint32_t pack_bf16(float lo, float hi) {
    __nv_bfloat162 h = __floats2bfloat162_rn(lo, hi);
    return *reinterpret_cast<uint32_t*>(&h);
}

#define LDSM4(r0, r1, r2, r3, addr)                                              \
    asm volatile("ldmatrix.sync.aligned.m8n8.x4.shared.b16 {%0,%1,%2,%3}, [%4];" \
                 : "=r"(r0), "=r"(r1), "=r"(r2), "=r"(r3) : "r"(addr))

static __device__ __forceinline__ void mma16816(float c[4],
        uint32_t a0, uint32_t a1, uint32_t a2, uint32_t a3,
        uint32_t b0, uint32_t b1) {
    asm volatile(
        "mma.sync.aligned.m16n8k16.row.col.f32.bf16.bf16.f32 "
        "{%0,%1,%2,%3}, {%4,%5,%6,%7}, {%8,%9}, {%0,%1,%2,%3};"
        : "+f"(c[0]), "+f"(c[1]), "+f"(c[2]), "+f"(c[3])
        : "r"(a0), "r"(a1), "r"(a2), "r"(a3), "r"(b0), "r"(b1));
}

static __device__ __forceinline__ void sts128v(uint32_t addr, uint32_t a, uint32_t b,
                                               uint32_t c, uint32_t d) {
    asm volatile("st.shared.v4.b32 [%0], {%1,%2,%3,%4};"
                 :: "r"(addr), "r"(a), "r"(b), "r"(c), "r"(d) : "memory");
}
static __device__ __forceinline__ void sts32(uint32_t addr, uint32_t v) {
    asm volatile("st.shared.b32 [%0], %1;" :: "r"(addr), "r"(v) : "memory");
}
#define BAR_WG1() asm volatile("bar.sync 1, 128;" ::: "memory")

// ---- GEMM1: dst = relu(src @ W + be), 64x128x128, warp owns 32 N-cols, 4 m-tiles ----
static __device__ __forceinline__ void gemm_g1(
    uint32_t srcb, uint32_t dstb, const uint32_t (&B)[4][8][2], const float* be,
    int wg, uint32_t lrowoff, uint32_t r_lo, uint32_t khalf,
    uint32_t erow, uint32_t ecolq)
{
    #pragma unroll 1
    for (int mt = 0; mt < 4; mt++) {
        float c[4][4];
        #pragma unroll
        for (int nt = 0; nt < 4; nt++)
            #pragma unroll
            for (int q = 0; q < 4; q++) c[nt][q] = 0.f;

        const uint32_t abase = srcb + (uint32_t)mt * 4096 + lrowoff;
        #pragma unroll
        for (int kc = 0; kc < 8; kc++) {
            uint32_t a0, a1, a2, a3;
            LDSM4(a0, a1, a2, a3, abase + ((((uint32_t)(kc * 2) + khalf) ^ r_lo) << 4));
            #pragma unroll
            for (int nt = 0; nt < 4; nt++)
                mma16816(c[nt], a0, a1, a2, a3, B[nt][kc][0], B[nt][kc][1]);
        }
        const uint32_t row0 = (uint32_t)mt * 16 + erow;
        const uint32_t dst0 = dstb + row0 * 256;
        #pragma unroll
        for (int nt = 0; nt < 4; nt++) {
            int col = wg * 32 + nt * 8 + (int)ecolq * 2;
            float bea = be[col], beb = be[col + 1];
            float v0 = fmaxf(c[nt][0] + bea, 0.f);
            float v1 = fmaxf(c[nt][1] + beb, 0.f);
            float v2 = fmaxf(c[nt][2] + bea, 0.f);
            float v3 = fmaxf(c[nt][3] + beb, 0.f);
            uint32_t chunk = (uint32_t)(wg * 4 + nt);
            uint32_t a0addr = dst0 + ((chunk ^ erow) << 4) + ecolq * 4;
            sts32(a0addr,        pack_bf16(v0, v1));
            sts32(a0addr + 2048, pack_bf16(v2, v3));   // row0 + 8
        }
    }
}

// ---- GEMM2 + fused layer3 dot: pred partials per warp into fPP ----
static __device__ __forceinline__ void gemm_g2(
    uint32_t srcb, const uint32_t (&B)[4][8][2], const float* be,
    const float* w3a, const float* w3b, float2* fPP,
    int wg, uint32_t lrowoff, uint32_t r_lo, uint32_t khalf,
    uint32_t erow, uint32_t ecolq)
{
    #pragma unroll 1
    for (int mt = 0; mt < 4; mt++) {
        float c[4][4];
        #pragma unroll
        for (int nt = 0; nt < 4; nt++)
            #pragma unroll
            for (int q = 0; q < 4; q++) c[nt][q] = 0.f;

        const uint32_t abase = srcb + (uint32_t)mt * 4096 + lrowoff;
        #pragma unroll
        for (int kc = 0; kc < 8; kc++) {
            uint32_t a0, a1, a2, a3;
            LDSM4(a0, a1, a2, a3, abase + ((((uint32_t)(kc * 2) + khalf) ^ r_lo) << 4));
            #pragma unroll
            for (int nt = 0; nt < 4; nt++)
                mma16816(c[nt], a0, a1, a2, a3, B[nt][kc][0], B[nt][kc][1]);
        }

        float pA0 = 0.f, pA1 = 0.f, pB0 = 0.f, pB1 = 0.f;
        #pragma unroll
        for (int nt = 0; nt < 4; nt++) {
            int col = wg * 32 + nt * 8 + (int)ecolq * 2;
            float bea = be[col], beb = be[col + 1];
            float wa0 = w3a[col], wa1 = w3a[col + 1];
            float wb0 = w3b[col], wb1 = w3b[col + 1];
            float v0 = fmaxf(c[nt][0] + bea, 0.f);
            float v1 = fmaxf(c[nt][1] + beb, 0.f);
            float v2 = fmaxf(c[nt][2] + bea, 0.f);
            float v3 = fmaxf(c[nt][3] + beb, 0.f);
            pA0 = fmaf(v0, wa0, fmaf(v1, wa1, pA0));
            pA1 = fmaf(v0, wb0, fmaf(v1, wb1, pA1));
            pB0 = fmaf(v2, wa0, fmaf(v3, wa1, pB0));
            pB1 = fmaf(v2, wb0, fmaf(v3, wb1, pB1));
        }
        pA0 += __shfl_xor_sync(0xffffffffu, pA0, 1);
        pA1 += __shfl_xor_sync(0xffffffffu, pA1, 1);
        pB0 += __shfl_xor_sync(0xffffffffu, pB0, 1);
        pB1 += __shfl_xor_sync(0xffffffffu, pB1, 1);
        pA0 += __shfl_xor_sync(0xffffffffu, pA0, 2);
        pA1 += __shfl_xor_sync(0xffffffffu, pA1, 2);
        pB0 += __shfl_xor_sync(0xffffffffu, pB0, 2);
        pB1 += __shfl_xor_sync(0xffffffffu, pB1, 2);
        if (ecolq == 0) {
            int r = mt * 16 + (int)erow;
            fPP[wg * 64 + r]     = make_float2(pA0, pA1);
            fPP[wg * 64 + r + 8] = make_float2(pB0, pB1);
        }
    }
}

// ---- layer0 for one row-half: 64 cols ----
static __device__ __forceinline__ void layer0_row(
    uint32_t h1buf, float2 xv, const float* fA, const float* be0, int half, int row)
{
    const uint32_t rowbase = h1buf + (uint32_t)row * 256;
    const uint32_t rx = (uint32_t)(row & 7);
    const int j0 = half * 64;
    #pragma unroll
    for (int jj = 0; jj < 64; jj += 8) {
        int j = j0 + jj;
        float4 wa0 = *(const float4*)&fA[F_W0A + j];
        float4 wa1 = *(const float4*)&fA[F_W0A + j + 4];
        float4 wb0 = *(const float4*)&fA[F_W0B + j];
        float4 wb1 = *(const float4*)&fA[F_W0B + j + 4];
        float4 b0v = *(const float4*)&be0[j];
        float4 b1v = *(const float4*)&be0[j + 4];
        float v0 = fmaxf(fmaf(xv.x, wa0.x, fmaf(xv.y, wb0.x, b0v.x)), 0.f);
        float v1 = fmaxf(fmaf(xv.x, wa0.y, fmaf(xv.y, wb0.y, b0v.y)), 0.f);
        float v2 = fmaxf(fmaf(xv.x, wa0.z, fmaf(xv.y, wb0.z, b0v.z)), 0.f);
        float v3 = fmaxf(fmaf(xv.x, wa0.w, fmaf(xv.y, wb0.w, b0v.w)), 0.f);
        float v4 = fmaxf(fmaf(xv.x, wa1.x, fmaf(xv.y, wb1.x, b1v.x)), 0.f);
        float v5 = fmaxf(fmaf(xv.x, wa1.y, fmaf(xv.y, wb1.y, b1v.y)), 0.f);
        float v6 = fmaxf(fmaf(xv.x, wa1.z, fmaf(xv.y, wb1.z, b1v.z)), 0.f);
        float v7 = fmaxf(fmaf(xv.x, wa1.w, fmaf(xv.y, wb1.w, b1v.w)), 0.f);
        uint32_t addr = rowbase + ((((uint32_t)(j >> 3)) ^ rx) << 4);
        sts128v(addr, pack_bf16(v0, v1), pack_bf16(v2, v3),
                      pack_bf16(v4, v5), pack_bf16(v6, v7));
    }
}

__global__ void __launch_bounds__(NTHREADS, 2)
ddpm_kernel(const float* __restrict__ noise, const float* __restrict__ z,
            const float* __restrict__ W0, const float* __restrict__ b0,
            const float* __restrict__ W1, const float* __restrict__ b1,
            const float* __restrict__ W2, const float* __restrict__ b2,
            const float* __restrict__ W3, const float* __restrict__ b3,
            const float* __restrict__ E0, const float* __restrict__ E1,
            const float* __restrict__ E2, float* __restrict__ out)
{
    extern __shared__ char smem_raw[];
    const uint32_t sb = smem_u32(smem_raw);
    float* fA = (float*)(smem_raw + SM_F32);
    float2* fXS = (float2*)&fA[F_XS];   // [2][64]
    float2* fPP = (float2*)&fA[F_PP];   // [4][64]

    const int tid  = threadIdx.x;
    const int lane = tid & 31;
    const int w    = tid >> 5;
    const bool isWG0 = (w < 4);
    const int wg   = w & 3;

    // ---- prologue ----
    if (tid < 128) {
        fA[F_W0A + tid] = W0[tid];
        fA[F_W0B + tid] = W0[NU + tid];
        fA[F_W3A + tid] = W3[2 * tid];
        fA[F_W3B + tid] = W3[2 * tid + 1];
        fA[F_BE0 + tid] = b0[tid] + E0[99 * NU + tid];   // step 0 (t=99)
        fA[F_BE1 + tid] = b1[tid] + E1[99 * NU + tid];
        fA[F_BE2 + tid] = b2[tid] + E2[99 * NU + tid];
    }
    if (tid < 2) fA[F_B3 + tid] = b3[tid];
    if (tid == 0) {
        double prod = 1.0;
        for (int t = 0; t < NSTEPS; t++) {
            double xl = -6.0 + 12.0 * (double)t / 99.0;
            double beta = (1.0 / (1.0 + exp(-xl))) * (0.005 - 1e-5) + 1e-5;
            double alpha = 1.0 - beta;
            prod *= alpha;
            fA[F_COEF + t]  = (float)(beta / sqrt(1.0 - prod));
            fA[F_INVAS + t] = (float)(1.0 / sqrt(alpha));
            fA[F_BSQ + t]   = (float)sqrt(beta);
        }
    }
    // x init (fXS flat index = tile*64+row = tid for tid<128)
    if (tid < 128) {
        int sample = blockIdx.x * CTA_SAMPLES + tid;
        float2 nv = (sample < BTOT) ? ((const float2*)noise)[sample] : make_float2(0.f, 0.f);
        fXS[tid] = nv;
    }

    // ---- weight fragments: WG0 <- W1, WG1 <- W2 (32-col slice per warp) ----
    uint32_t Bw[4][8][2];
    {
        const float* Wsrc = isWG0 ? W1 : W2;
        const int n0 = wg * 32 + (lane >> 2);
        const int kb = (lane & 3) * 2;
        #pragma unroll
        for (int nt = 0; nt < 4; nt++) {
            int n = n0 + nt * 8;
            #pragma unroll
            for (int kc = 0; kc < 8; kc++) {
                int k0 = kc * 16 + kb;
                Bw[nt][kc][0] = pack_bf16(Wsrc[k0 * NU + n],       Wsrc[(k0 + 1) * NU + n]);
                Bw[nt][kc][1] = pack_bf16(Wsrc[(k0 + 8) * NU + n], Wsrc[(k0 + 9) * NU + n]);
            }
        }
    }

    // per-lane ldmatrix / epilogue constants
    const uint32_t r_lo    = (uint32_t)(lane & 7);
    const uint32_t half_l  = (uint32_t)((lane >> 3) & 1);
    const uint32_t khalf   = (uint32_t)(lane >> 4);
    const uint32_t lrowoff = (half_l * 8 + r_lo) * 256;
    const uint32_t erow    = (uint32_t)(lane >> 2);
    const uint32_t ecolq   = (uint32_t)(lane & 3);

    __syncthreads();

    // ---- U0: layer0 for both tiles (256 threads, 128 rows x 2 halves) ----
    {
        int idx  = tid & 127;
        int tile = tid >> 7;
        int row  = idx & 63;
        int half = idx >> 6;
        uint32_t h1 = sb + (tile ? SM_H1B : SM_H1A);
        layer0_row(h1, fXS[tile * 64 + row], fA, &fA[F_BE0], half, row);
    }
    __syncthreads();

    // ---- prologue GEMM1(b, step 0) ----
    if (isWG0)
        gemm_g1(sb + SM_H1B, sb + SM_H2B, Bw, &fA[F_BE1], wg,
                lrowoff, r_lo, khalf, erow, ecolq);
    __syncthreads();

    // ---- main loop ----
    #pragma unroll 1
    for (int k = 0; k < NSTEPS; k++) {
        const int par  = k & 1;
        const int parn = par ^ 1;
        const int t    = 99 - k;
        const bool last = (k == NSTEPS - 1);

        // ================= slot A: G1(a,k) || G2(b,k)+U(b,k+1) =================
        if (isWG0) {
            if (!last)
                fA[F_BE1 + parn * 128 + tid] = b1[tid] + E1[(t - 1) * NU + tid];
            gemm_g1(sb + SM_H1A, sb + SM_H2A, Bw, &fA[F_BE1 + par * 128], wg,
                    lrowoff, r_lo, khalf, erow, ecolq);
        } else {
            const int tid2 = tid - 128;
            const int row  = tid2 & 63;
            const int half = tid2 >> 6;
            if (!last) {
                fA[F_BE0 + parn * 128 + tid2] = b0[tid2] + E0[(t - 1) * NU + tid2];
                fA[F_BE2 + parn * 128 + tid2] = b2[tid2] + E2[(t - 1) * NU + tid2];
            }
            float zc0 = 0.f, zc1 = 0.f;
            {
                int sampleB = blockIdx.x * CTA_SAMPLES + 64 + row;
                if (half == 0 && sampleB < BTOT) {
                    float2 zz = ((const float2*)z)[(size_t)k * BTOT + sampleB];
                    zc0 = zz.x; zc1 = zz.y;
                }
            }
            gemm_g2(sb + SM_H2B, Bw, &fA[F_BE2 + par * 128],
                    &fA[F_W3A], &fA[F_W3B], fPP, wg,
                    lrowoff, r_lo, khalf, erow, ecolq);
            BAR_WG1();
            if (half == 0) {
                float p0 = fA[F_B3], p1 = fA[F_B3 + 1];
                #pragma unroll
                for (int g = 0; g < 4; g++) {
                    float2 v = fPP[g * 64 + row];
                    p0 += v.x; p1 += v.y;
                }
                float cf = fA[F_COEF + t], ia = fA[F_INVAS + t], bq = fA[F_BSQ + t];
                float2 xv = fXS[64 + row];
                float nx0 = (xv.x - cf * p0) * ia + bq * zc0;
                float nx1 = (xv.y - cf * p1) * ia + bq * zc1;
                if (last) {
                    int sampleB = blockIdx.x * CTA_SAMPLES + 64 + row;
                    if (sampleB < BTOT) ((float2*)out)[sampleB] = make_float2(nx0, nx1);
                } else {
                    fXS[64 + row] = make_float2(nx0, nx1);
                }
            }
            if (!last) {
                BAR_WG1();
                layer0_row(sb + SM_H1B, fXS[64 + row], fA, &fA[F_BE0 + parn * 128], half, row);
            }
        }
        __syncthreads();

        // ================= slot B: G1(b,k+1) || G2(a,k)+U(a,k+1) =================
        if (isWG0) {
            if (!last)
                gemm_g1(sb + SM_H1B, sb + SM_H2B, Bw, &fA[F_BE1 + parn * 128], wg,
                        lrowoff, r_lo, khalf, erow, ecolq);
        } else {
            const int tid2 = tid - 128;
            const int row  = tid2 & 63;
            const int half = tid2 >> 6;
            float zc0 = 0.f, zc1 = 0.f;
            {
                int sampleA = blockIdx.x * CTA_SAMPLES + row;
                if (half == 0 && sampleA < BTOT) {
                    float2 zz = ((const float2*)z)[(size_t)k * BTOT + sampleA];
                    zc0 = zz.x; zc1 = zz.y;
                }
            }
            gemm_g2(sb + SM_H2A, Bw, &fA[F_BE2 + par * 128],
                    &fA[F_W3A], &fA[F_W3B], fPP, wg,
                    lrowoff, r_lo, khalf, erow, ecolq);
            BAR_WG1();
            if (half == 0) {
                float p0 = fA[F_B3], p1 = fA[F_B3 + 1];
                #pragma unroll
                for (int g = 0; g < 4; g++) {
                    float2 v = fPP[g * 64 + row];
                    p0 += v.x; p1 += v.y;
                }
                float cf = fA[F_COEF + t], ia = fA[F_INVAS + t], bq = fA[F_BSQ + t];
                float2 xv = fXS[row];
                float nx0 = (xv.x - cf * p0) * ia + bq * zc0;
                float nx1 = (xv.y - cf * p1) * ia + bq * zc1;
                if (last) {
                    int sampleA = blockIdx.x * CTA_SAMPLES + row;
                    if (sampleA < BTOT) ((float2*)out)[sampleA] = make_float2(nx0, nx1);
                } else {
                    fXS[row] = make_float2(nx0, nx1);
                }
            }
            if (!last) {
                BAR_WG1();
                layer0_row(sb + SM_H1A, fXS[row], fA, &fA[F_BE0 + parn * 128], half, row);
            }
        }
        __syncthreads();
    }
}

extern "C" void kernel_launch(void* const* d_in, const int* in_sizes, int n_in,
                              void* d_out, int out_size) {
    (void)in_sizes; (void)n_in; (void)out_size;
    const float* noise = (const float*)d_in[0];
    const float* z     = (const float*)d_in[1];
    const float* W0    = (const float*)d_in[2];
    const float* b0    = (const float*)d_in[3];
    const float* W1    = (const float*)d_in[4];
    const float* b1    = (const float*)d_in[5];
    const float* W2    = (const float*)d_in[6];
    const float* b2    = (const float*)d_in[7];
    const float* W3    = (const float*)d_in[8];
    const float* b3    = (const float*)d_in[9];
    const float* E0    = (const float*)d_in[10];
    const float* E1    = (const float*)d_in[11];
    const float* E2    = (const float*)d_in[12];
    float* out = (float*)d_out;

    cudaFuncSetAttribute(ddpm_kernel, cudaFuncAttributeMaxDynamicSharedMemorySize, SMEM_TOTAL);

    dim3 grid((BTOT + CTA_SAMPLES - 1) / CTA_SAMPLES);
    ddpm_kernel<<<grid, NTHREADS, SMEM_TOTAL>>>(noise, z, W0, b0, W1, b1, W2, b2,
                                                W3, b3, E0, E1, E2, out);
}